// round 14
// baseline (speedup 1.0000x reference)
#include <cuda_runtime.h>
#include <cuda_bf16.h>
#include <math.h>

// ---------------- problem constants ----------------
#define T_STEPS 512
#define BATCH   128
#define HDIM    300
#define MCELLS  20
#define ROWS    (BATCH*MCELLS)   // 2560
#define DECAY   0.98f
#define EPS_V   1e-8f

#define NTHREADS 256
#define NJOBS    600    // 3 matrices * 20rt*5ct * 2 K-halves  (P hoisted out)
#define PJOBS    (T_STEPS*15)   // one-time P precompute jobs
#define RH       (ROWS*HDIM)
#define PSZ      (BATCH*900)
// padded planar weight tables: 3 mem matrices 160 pairs x 320 cols, P 160 x 960
#define WB_MEMSZ  51200          // 160*320 per mem matrix
#define WB_POFF   153600         // 3*51200
#define WBTOT     307200         // + 160*960

// 1 = JAX >= 0.4.30 default (threefry_partitionable)
#define THREEFRY_PARTITIONABLE 1

// ---------------- device state (no allocation anywhere) ----------------
__device__ float g_mem[RH];             // (B,M,H)
__device__ float g_usage[ROWS];         // (B,M)
__device__ float g_HPa [RH];            // mem@Ws1[0:300], K 0..160
__device__ float g_HPb [RH];            // K 160..300
__device__ float g_HP2a[RH];            // (h*mem)@Ws1[600:900] halves
__device__ float g_HP2b[RH];
__device__ float g_CPa [RH];            // mem@Wu[300:600] halves
__device__ float g_CPb [RH];
__device__ float g_Pall[(size_t)T_STEPS*PSZ];  // h_t@[We1|Ws1mid|Wu0] all steps
__device__ float g_cand[RH];            // tanh(CPa+CPb + P6 + bu)
__device__ float g_ow[ROWS];
__device__ float g_indv[ROWS];
__device__ unsigned g_WBh[WBTOT];       // hi bf16-pairs (padded, planar)
__device__ unsigned g_WBl[WBTOT];       // lo bf16-pairs
__device__ unsigned g_count;            // grid-barrier counter
__device__ unsigned g_pctr;             // one-time P job counter
__device__ unsigned g_jobctr[T_STEPS];  // per-step dynamic job counters

// ---------------- dynamic smem tile buffers ----------------
// row stride 24 bf16 (48 B): 16 data + 8 pad -> ldmatrix conflict-free.
struct SmemT {
    unsigned short SAh[2][128][24];
    unsigned short SAl[2][128][24];
    unsigned short SBh[2][64][24];
    unsigned short SBl[2][64][24];
};

// ---------------- software grid barrier ----------------
__device__ __forceinline__ void grid_bar(unsigned &target, int nblk) {
    __syncthreads();
    if (threadIdx.x == 0) {
        target += (unsigned)nblk;
        __threadfence();
        atomicAdd(&g_count, 1u);
        volatile unsigned* p = &g_count;
        while (*p < target) { }
        __threadfence();
    }
    __syncthreads();
}

// ---------------- JAX threefry-2x32-20 noise ----------------
__device__ __forceinline__ void tf_round(unsigned &x0, unsigned &x1, int r) {
    x0 += x1;
    x1 = (x1 << r) | (x1 >> (32 - r));
    x1 ^= x0;
}
__device__ __forceinline__ void threefry2x32(unsigned c0, unsigned c1,
                                             unsigned &o0, unsigned &o1) {
    const unsigned k0 = 0u, k1 = 42u, k2 = 0x1BD11BDAu ^ 0u ^ 42u;
    unsigned x0 = c0 + k0, x1 = c1 + k1;
    tf_round(x0,x1,13); tf_round(x0,x1,15); tf_round(x0,x1,26); tf_round(x0,x1,6);
    x0 += k1; x1 += k2 + 1u;
    tf_round(x0,x1,17); tf_round(x0,x1,29); tf_round(x0,x1,16); tf_round(x0,x1,24);
    x0 += k2; x1 += k0 + 2u;
    tf_round(x0,x1,13); tf_round(x0,x1,15); tf_round(x0,x1,26); tf_round(x0,x1,6);
    x0 += k0; x1 += k1 + 3u;
    tf_round(x0,x1,17); tf_round(x0,x1,29); tf_round(x0,x1,16); tf_round(x0,x1,24);
    x0 += k1; x1 += k2 + 4u;
    tf_round(x0,x1,13); tf_round(x0,x1,15); tf_round(x0,x1,26); tf_round(x0,x1,6);
    x0 += k2; x1 += k0 + 5u;
    o0 = x0; o1 = x1;
}
__device__ __forceinline__ float jax_noise(unsigned i) {
    unsigned bits;
#if THREEFRY_PARTITIONABLE
    unsigned o0, o1;
    threefry2x32(0u, i, o0, o1);
    bits = o0 ^ o1;
#else
    const unsigned half = (unsigned)(T_STEPS*BATCH*MCELLS) / 2u;
    unsigned o0, o1;
    if (i < half) { threefry2x32(i, i + half, o0, o1); bits = o0; }
    else          { threefry2x32(i - half, i, o0, o1); bits = o1; }
#endif
    float f = __uint_as_float((bits >> 9) | 0x3f800000u) - 1.0f;
    float u = __fadd_rn(__fmul_rn(f, 0.99f), 0.01f);
    return fmaxf(0.01f, u);
}

// ---------------- warp reductions ----------------
__device__ __forceinline__ float warpSum(float v) {
#pragma unroll
    for (int o = 16; o; o >>= 1) v += __shfl_xor_sync(0xffffffffu, v, o);
    return v;
}
__device__ __forceinline__ float warpMax(float v) {
#pragma unroll
    for (int o = 16; o; o >>= 1) v = fmaxf(v, __shfl_xor_sync(0xffffffffu, v, o));
    return v;
}

// fast tanh: abs err ~1e-6; __expf(inf)->inf gives exact saturation
__device__ __forceinline__ float tanh_fast(float x) {
    float ax = fabsf(x);
    float e  = __expf(2.0f * ax);
    float r  = 1.0f - __fdividef(2.0f, e + 1.0f);
    return copysignf(r, x);
}

// ---------------- bf16 split + async copy helpers ----------------
__device__ __forceinline__ unsigned pack_bf16x2(float e, float o) {
    unsigned r;
    asm("cvt.rn.bf16x2.f32 %0, %1, %2;" : "=r"(r) : "f"(o), "f"(e));
    return r;
}
__device__ __forceinline__ void bsplit(float x, float &hf, float &lf) {
    __nv_bfloat16 h = __float2bfloat16(x);
    hf = __bfloat162float(h);
    lf = x - hf;
}
__device__ __forceinline__ unsigned smem_u32(const void* p) {
    return (unsigned)__cvta_generic_to_shared(p);
}
__device__ __forceinline__ void cp4(unsigned dst, const void* src) {
    asm volatile("cp.async.ca.shared.global [%0], [%1], 4;"
                 :: "r"(dst), "l"(src));
}
__device__ __forceinline__ void cp_commit() {
    asm volatile("cp.async.commit_group;" ::: "memory");
}
__device__ __forceinline__ void cp_wait0() {
    asm volatile("cp.async.wait_group 0;" ::: "memory");
}
__device__ __forceinline__ void ldsm4(unsigned r[4], unsigned addr) {
    asm volatile("ldmatrix.sync.aligned.m8n8.x4.shared.b16 {%0,%1,%2,%3}, [%4];"
        : "=r"(r[0]), "=r"(r[1]), "=r"(r[2]), "=r"(r[3]) : "r"(addr));
}
__device__ __forceinline__ void mma_bf16(float c[4],
    unsigned a0, unsigned a1, unsigned a2, unsigned a3,
    unsigned b0, unsigned b1)
{
    asm("mma.sync.aligned.m16n8k16.row.col.f32.bf16.bf16.f32 "
        "{%0,%1,%2,%3}, {%4,%5,%6,%7}, {%8,%9}, {%0,%1,%2,%3};"
        : "+f"(c[0]), "+f"(c[1]), "+f"(c[2]), "+f"(c[3])
        : "r"(a0), "r"(a1), "r"(a2), "r"(a3), "r"(b0), "r"(b1));
}

// ---------------- shared GEMM core (BM=128, BN=64, BK=16, bf16 hi/lo 3-term) ----
// B staged via cp.async from padded planar tables (no predicates).
__device__ __forceinline__ void gemm_core(
    const float* aRow0, const float* aRow1,
    const float* h0, const float* h1, bool domul,
    const unsigned* __restrict__ whcol, const unsigned* __restrict__ wlcol,
    int wstride, int kstart, int nstage,
    float* dst, int ncols, int c0, SmemT* sm)
{
    const int tid = threadIdx.x;
    const int ar0 = tid >> 2, aq4 = (tid & 3) * 4;  // A: rows ar0/ar0+64, k-quad
    const int bn = tid & 63, bp = tid >> 6;         // B: col, pair-group
    const int pstart = kstart >> 1;

    const int warp = tid >> 5, lane = tid & 31;
    const int m0 = (warp >> 1) * 32;
    const int n0 = (warp & 1) * 32;
    const int lg = lane >> 2, lt = lane & 3;

    // ldmatrix lane-dependent byte offsets (row stride 24 bf16 = 48 B)
    const int lrowA = (lane & 7) + ((lane & 8) ? 8 : 0);
    const int lkA   = (lane & 16) ? 8 : 0;
    unsigned aoff[2];
#pragma unroll
    for (int mi = 0; mi < 2; mi++)
        aoff[mi] = (unsigned)(((m0 + mi*16 + lrowA) * 24 + lkA) * 2);
    const int lrowB = (lane & 7) + ((lane & 16) ? 8 : 0);
    const int lkB   = (lane & 8) ? 8 : 0;
    unsigned boff[2];
#pragma unroll
    for (int nip = 0; nip < 2; nip++)
        boff[nip] = (unsigned)(((n0 + nip*16 + lrowB) * 24 + lkB) * 2);

    unsigned baseSAh[2] = { smem_u32(&sm->SAh[0][0][0]), smem_u32(&sm->SAh[1][0][0]) };
    unsigned baseSAl[2] = { smem_u32(&sm->SAl[0][0][0]), smem_u32(&sm->SAl[1][0][0]) };
    unsigned baseSBh[2] = { smem_u32(&sm->SBh[0][0][0]), smem_u32(&sm->SBh[1][0][0]) };
    unsigned baseSBl[2] = { smem_u32(&sm->SBl[0][0][0]), smem_u32(&sm->SBl[1][0][0]) };

    // cp.async destination addresses (per buffer)
    unsigned dBh0[2], dBh1[2], dBl0[2], dBl1[2];
#pragma unroll
    for (int buf = 0; buf < 2; buf++) {
        unsigned rowoff = (unsigned)(bn * 24 * 2);
        dBh0[buf] = baseSBh[buf] + rowoff + (unsigned)(2*bp)*2u;
        dBh1[buf] = baseSBh[buf] + rowoff + (unsigned)(2*bp + 8)*2u;
        dBl0[buf] = baseSBl[buf] + rowoff + (unsigned)(2*bp)*2u;
        dBl1[buf] = baseSBl[buf] + rowoff + (unsigned)(2*bp + 8)*2u;
    }

    float c[2][4][4];
#pragma unroll
    for (int mi = 0; mi < 2; mi++)
#pragma unroll
        for (int ni = 0; ni < 4; ni++)
#pragma unroll
            for (int q = 0; q < 4; q++) c[mi][ni][q] = 0.f;

    float4 ra0, ra1;
    auto cpB = [&](int s, int buf) {
        int p0 = pstart + s*8 + bp;
        const unsigned* sh = whcol + (size_t)p0 * wstride;
        const unsigned* sl = wlcol + (size_t)p0 * wstride;
        cp4(dBh0[buf], sh);
        cp4(dBh1[buf], sh + 4*(size_t)wstride);
        cp4(dBl0[buf], sl);
        cp4(dBl1[buf], sl + 4*(size_t)wstride);
    };
    auto ldA = [&](int s) {
        int kg = kstart + s*16 + aq4;
        if (kg < 300) {
            ra0 = *(const float4*)(aRow0 + kg);
            ra1 = *(const float4*)(aRow1 + kg);
            if (domul) {
                float4 f0 = *(const float4*)(h0 + kg);
                float4 f1 = *(const float4*)(h1 + kg);
                ra0.x *= f0.x; ra0.y *= f0.y; ra0.z *= f0.z; ra0.w *= f0.w;
                ra1.x *= f1.x; ra1.y *= f1.y; ra1.z *= f1.z; ra1.w *= f1.w;
            }
        } else {
            ra0 = make_float4(0.f,0.f,0.f,0.f);
            ra1 = make_float4(0.f,0.f,0.f,0.f);
        }
    };
    auto stA = [&](int buf) {
        float hx,lx,hy,ly,hz,lz,hw,lw;
        bsplit(ra0.x,hx,lx); bsplit(ra0.y,hy,ly);
        bsplit(ra0.z,hz,lz); bsplit(ra0.w,hw,lw);
        *(uint2*)&sm->SAh[buf][ar0][aq4] =
            make_uint2(pack_bf16x2(hx,hy), pack_bf16x2(hz,hw));
        *(uint2*)&sm->SAl[buf][ar0][aq4] =
            make_uint2(pack_bf16x2(lx,ly), pack_bf16x2(lz,lw));
        bsplit(ra1.x,hx,lx); bsplit(ra1.y,hy,ly);
        bsplit(ra1.z,hz,lz); bsplit(ra1.w,hw,lw);
        *(uint2*)&sm->SAh[buf][ar0+64][aq4] =
            make_uint2(pack_bf16x2(hx,hy), pack_bf16x2(hz,hw));
        *(uint2*)&sm->SAl[buf][ar0+64][aq4] =
            make_uint2(pack_bf16x2(lx,ly), pack_bf16x2(lz,lw));
    };

    // prologue
    cpB(0, 0); cp_commit();
    ldA(0);
    stA(0);
    cp_wait0();
    __syncthreads();

    for (int s = 0; s < nstage; s++) {
        int cur = s & 1;
        bool more = (s + 1 < nstage);
        if (more) { cpB(s + 1, cur ^ 1); cp_commit(); ldA(s + 1); }

        unsigned Ah[2][4], Al[2][4], Bh[2][4], Bl[2][4];
#pragma unroll
        for (int mi = 0; mi < 2; mi++) {
            ldsm4(Ah[mi], baseSAh[cur] + aoff[mi]);
            ldsm4(Al[mi], baseSAl[cur] + aoff[mi]);
        }
#pragma unroll
        for (int nip = 0; nip < 2; nip++) {
            ldsm4(Bh[nip], baseSBh[cur] + boff[nip]);
            ldsm4(Bl[nip], baseSBl[cur] + boff[nip]);
        }
#pragma unroll
        for (int mi = 0; mi < 2; mi++)
#pragma unroll
            for (int ni = 0; ni < 4; ni++) {
                int nip = ni >> 1, sel = (ni & 1) * 2;
                unsigned bh0 = Bh[nip][sel], bh1 = Bh[nip][sel+1];
                unsigned bl0 = Bl[nip][sel], bl1 = Bl[nip][sel+1];
                mma_bf16(c[mi][ni], Ah[mi][0], Ah[mi][1], Ah[mi][2], Ah[mi][3],
                         bh0, bh1);
                mma_bf16(c[mi][ni], Ah[mi][0], Ah[mi][1], Ah[mi][2], Ah[mi][3],
                         bl0, bl1);
                mma_bf16(c[mi][ni], Al[mi][0], Al[mi][1], Al[mi][2], Al[mi][3],
                         bh0, bh1);
            }

        if (more) stA(cur ^ 1);
        cp_wait0();
        __syncthreads();
    }

#pragma unroll
    for (int mi = 0; mi < 2; mi++)
#pragma unroll
        for (int ni = 0; ni < 4; ni++) {
            int row = m0 + mi*16 + lg;
            int col = c0 + n0 + ni*8 + 2*lt;
            if (col < ncols) {
                dst[row*ncols + col]     = c[mi][ni][0];
                dst[(row+8)*ncols + col] = c[mi][ni][2];
            }
            if (col + 1 < ncols) {
                dst[row*ncols + col + 1]     = c[mi][ni][1];
                dst[(row+8)*ncols + col + 1] = c[mi][ni][3];
            }
        }
}

// ---------------- per-step GEMM job (mem-dependent matrices only) ----------------
__device__ __forceinline__ void gemm_job(
    int job, int t, const float* __restrict__ hs, SmemT* sm)
{
    const int tid = threadIdx.x;
    const float* hbase = hs + (size_t)t * BATCH * HDIM;

    const int mtype = job / 200;
    int e = job % 200;  const int kh = e & 1;  int e2 = e >> 1;
    const int r0 = (e2 / 5) * 128, c0 = (e2 % 5) * 64;
    const int kstart = kh ? 160 : 0;
    const int nstage = kh ? 9 : 10;

    const int ar0 = tid >> 2;
    const float* aRow0 = g_mem + (r0 + ar0) * HDIM;
    const float* aRow1 = g_mem + (r0 + ar0 + 64) * HDIM;
    const float* h0 = hbase + ((r0 + ar0) / MCELLS) * HDIM;
    const float* h1 = hbase + ((r0 + ar0 + 64) / MCELLS) * HDIM;

    const int jg = c0 + (tid & 63);
    const unsigned* whcol = g_WBh + mtype * WB_MEMSZ + jg;
    const unsigned* wlcol = g_WBl + mtype * WB_MEMSZ + jg;

    float* dstbase;
    if (mtype == 0)      dstbase = kh ? g_HPb  : g_HPa;
    else if (mtype == 1) dstbase = kh ? g_HP2b : g_HP2a;
    else                 dstbase = kh ? g_CPb  : g_CPa;

    gemm_core(aRow0, aRow1, h0, h1, (mtype == 1), whcol, wlcol, 320,
              kstart, nstage, dstbase + r0*300, 300, c0, sm);
}

// ---------------- one-time P GEMM job ----------------
__device__ __forceinline__ void pgemm_job(
    int job, const float* __restrict__ hs, SmemT* sm)
{
    const int tid = threadIdx.x;
    const int t = job / 15;
    const int c0 = (job % 15) * 64;
    const float* hbase = hs + (size_t)t * BATCH * HDIM;

    const int ar0 = tid >> 2;
    const float* aRow0 = hbase + ar0 * HDIM;
    const float* aRow1 = hbase + (ar0 + 64) * HDIM;

    const int jg = c0 + (tid & 63);
    const unsigned* whcol = g_WBh + WB_POFF + jg;
    const unsigned* wlcol = g_WBl + WB_POFF + jg;

    gemm_core(aRow0, aRow1, (const float*)0, (const float*)0, false,
              whcol, wlcol, 960, 0, 19,
              g_Pall + (size_t)t*PSZ, 900, c0, sm);
}

// ---------------- gating job (block handles batch b) ----------------
__device__ __forceinline__ void gate_job(
    int b, int t,
    const float* __restrict__ mask,
    const float* __restrict__ be1, const float* __restrict__ We2,
    const float* __restrict__ be2, const float* __restrict__ bs1,
    const float* __restrict__ Ws2, const float* __restrict__ bs2,
    const float* __restrict__ Ws1,
    float* __restrict__ out,
    float (&s_sim)[MCELLS], float (&s_usage)[MCELLS],
    float (&s_red)[8], float &s_ent)
{
    const int tid = threadIdx.x;
    const int warp = tid >> 5, lane = tid & 31;

    const float* P = g_Pall + (size_t)t*PSZ + b*900;
    const float* wu_row = Ws1 + 900*300;

    if (tid < MCELLS) s_usage[tid] = g_usage[b*MCELLS + tid];
    __syncthreads();

    // ---- entity prob ----
    float acc = 0.f;
    for (int j = tid; j < 300; j += NTHREADS)
        acc += fmaxf(P[j] + be1[j], 0.f) * We2[j];
    acc = warpSum(acc);
    if (lane == 0) s_red[warp] = acc;
    __syncthreads();
    if (tid == 0) {
        float s = 0.f;
        for (int w = 0; w < 8; w++) s += s_red[w];
        float score = s + be2[0];
        float sig = 1.f / (1.f + expf(-score));
        s_ent = sig * mask[(size_t)t*BATCH + b];
    }

    // ---- sim[m] ----
    for (int m = warp; m < MCELLS; m += 8) {
        float u = s_usage[m];
        const int ro = (b*MCELLS + m)*300;
        float a = 0.f;
        for (int j = lane; j < 300; j += 32) {
            float pre = g_HPa[ro+j] + g_HPb[ro+j] + g_HP2a[ro+j] + g_HP2b[ro+j]
                      + P[300 + j] + u*wu_row[j] + bs1[j];
            a += fmaxf(pre, 0.f) * Ws2[j];
        }
        a = warpSum(a);
        if (lane == 0) s_sim[m] = a + bs2[0];
    }
    __syncthreads();

    // ---- gating (warp 0; lane = slot 0..20) ----
    if (warp == 0) {
        const unsigned FULL = 0xffffffffu;
        const int m = lane;
        const float NEG_INF = -INFINITY;
        float usg  = (m < MCELLS) ? s_usage[m] : 0.f;
        float simv = (m < MCELLS) ? s_sim[m]   : 0.f;

        float comb;
        if (m < MCELLS)       comb = (usg > 0.f) ? simv : -10000.f;
        else if (m == MCELLS) comb = 0.f;
        else                  comb = NEG_INF;
        float mx   = warpMax(comb);
        float ex   = (m <= MCELLS) ? expf(comb - mx) : 0.f;
        float esum = warpSum(ex);
        float prob = ex / esum;
        float mult = (m < MCELLS) ? ((usg > 0.f) ? 1.f : 0.f)
                                  : ((m == MCELLS) ? 1.f : 0.f);
        float maskedp = prob * mult;
        float msum = warpSum(maskedp);
        float nrm  = maskedp / (msum + EPS_V);
        float co   = s_ent * nrm;
        float ow_base = __shfl_sync(FULL, co, MCELLS);
        float indv = (m < MCELLS) ? co : 0.f;

        float s2  = (m < MCELLS) ? simv : NEG_INF;
        float mx2 = warpMax(s2);
        float e2  = (m < MCELLS) ? expf(simv - mx2) : 0.f;
        float es2 = warpSum(e2);
        float nsim = e2 / es2;

        float ow_score = (m < MCELLS)
            ? ((usg == 0.f ? nsim * 100000.f : 0.f) + (1.f - usg))
            : NEG_INF;
        float maxv = warpMax(ow_score);
        float nz   = (m < MCELLS && ow_score == maxv)
            ? jax_noise((unsigned)(((size_t)t*BATCH + b)*MCELLS + m)) : 0.f;
        float nzmax = warpMax(nz);
        unsigned ballot = __ballot_sync(FULL, (m < MCELLS) && (nz == nzmax));
        int idx = __ffs(ballot) - 1;

        float ow = (m == idx) ? ow_base : 0.f;
        float nu = fminf(1.f, ow + indv + DECAY * usg);

        float* out_ent = out;
        float* out_usg = out + (size_t)T_STEPS*BATCH;
        float* out_crf = out_usg + (size_t)T_STEPS*BATCH*MCELLS;
        float* out_ow  = out_crf + (size_t)T_STEPS*BATCH*MCELLS;
        if (m < MCELLS) {
            g_ow[b*MCELLS + m]    = ow;
            g_indv[b*MCELLS + m]  = indv;
            g_usage[b*MCELLS + m] = nu;
            size_t o = ((size_t)t*BATCH + b)*MCELLS + m;
            out_usg[o] = nu;
            out_crf[o] = indv * (1.f - EPS_V) + EPS_V;
            out_ow[o]  = ow   * (1.f - EPS_V) + EPS_V;
        }
        if (m == 0)
            out_ent[(size_t)t*BATCH + b] = s_ent * (1.f - EPS_V) + EPS_V;
    }
}

// ---------------- persistent kernel ----------------
__global__ __launch_bounds__(NTHREADS, 2) void k_persist(
    const float* __restrict__ hs, const float* __restrict__ mask,
    const float* __restrict__ We1, const float* __restrict__ be1,
    const float* __restrict__ We2, const float* __restrict__ be2,
    const float* __restrict__ Ws1, const float* __restrict__ bs1,
    const float* __restrict__ Ws2, const float* __restrict__ bs2,
    const float* __restrict__ Wu,  const float* __restrict__ bu,
    float* __restrict__ out, int nblk)
{
    extern __shared__ char smem_raw[];
    SmemT* sm = (SmemT*)smem_raw;

    __shared__ float s_sim[MCELLS], s_usage[MCELLS];
    __shared__ float s_red[8];
    __shared__ float s_ent;
    __shared__ int s_job;

    const int tid = threadIdx.x;
    unsigned target = 0;

    // ---- one-time: build padded planar bf16 split weight tables ----
    for (int idx = blockIdx.x*NTHREADS + tid; idx < WBTOT; idx += nblk*NTHREADS) {
        float v0 = 0.f, v1 = 0.f;
        if (idx < WB_POFF) {
            int mtype = idx / WB_MEMSZ;
            int e = idx % WB_MEMSZ;
            int p = e / 320, j = e % 320;
            int k0 = 2*p, k1 = 2*p + 1;
            if (j < 300 && k0 < 300) {
                if (mtype == 0)      { v0 = Ws1[k0*300 + j];
                                       if (k1 < 300) v1 = Ws1[k1*300 + j]; }
                else if (mtype == 1) { v0 = Ws1[(600+k0)*300 + j];
                                       if (k1 < 300) v1 = Ws1[(600+k1)*300 + j]; }
                else                 { v0 = Wu[(300+k0)*300 + j];
                                       if (k1 < 300) v1 = Wu[(300+k1)*300 + j]; }
            }
        } else {
            int e = idx - WB_POFF;
            int p = e / 960, j = e % 960;
            int k0 = 2*p, k1 = 2*p + 1;
            if (j < 900 && k0 < 300) {
                int role = j / 300, jc = j - role*300;
                if (role == 0)      { v0 = We1[k0*300 + jc];
                                      if (k1 < 300) v1 = We1[k1*300 + jc]; }
                else if (role == 1) { v0 = Ws1[(300+k0)*300 + jc];
                                      if (k1 < 300) v1 = Ws1[(300+k1)*300 + jc]; }
                else                { v0 = Wu[k0*300 + jc];
                                      if (k1 < 300) v1 = Wu[k1*300 + jc]; }
            }
        }
        float h0,l0,h1,l1;
        bsplit(v0, h0, l0);
        bsplit(v1, h1, l1);
        g_WBh[idx] = pack_bf16x2(h0, h1);
        g_WBl[idx] = pack_bf16x2(l0, l1);
    }
    grid_bar(target, nblk);

    // ---- one-time: precompute P for ALL steps (h-only GEMM) ----
    for (;;) {
        if (tid == 0) s_job = (int)atomicAdd(&g_pctr, 1u);
        __syncthreads();
        int job = s_job;
        __syncthreads();
        if (job >= PJOBS) break;
        pgemm_job(job, hs, sm);
    }
    grid_bar(target, nblk);

    for (int t = 0; t < T_STEPS; t++) {
        // ---- phase A: mem-dependent GEMMs (dynamic, tensor cores) ----
        for (;;) {
            if (tid == 0) s_job = (int)atomicAdd(&g_jobctr[t], 1u);
            __syncthreads();
            int job = s_job;
            __syncthreads();
            if (job >= NJOBS) break;
            gemm_job(job, t, hs, sm);
        }
        grid_bar(target, nblk);

        // ---- phase B: gate (blocks 0..127) || cand precompute (rest) ----
        if (blockIdx.x < BATCH) {
            gate_job(blockIdx.x, t, mask, be1, We2, be2, bs1, Ws2, bs2,
                     Ws1, out, s_sim, s_usage, s_red, s_ent);
        } else {
            const float4* CPa4 = (const float4*)g_CPa;
            const float4* CPb4 = (const float4*)g_CPb;
            const float4* Pt4  = (const float4*)(g_Pall + (size_t)t*PSZ);
            const float4* bu4  = (const float4*)bu;
            float4* cand4 = (float4*)g_cand;
            const int total = ROWS * 75;
            const int nb = nblk - BATCH;
            for (int idx = (blockIdx.x - BATCH)*NTHREADS + tid; idx < total;
                 idx += nb*NTHREADS) {
                int r  = idx / 75;
                int jq = idx - r*75;
                int b  = r / MCELLS;
                float4 ca = CPa4[idx], cb = CPb4[idx];
                float4 pa = Pt4[b*225 + 150 + jq];
                float4 bv = bu4[jq];
                float4 res;
                res.x = tanh_fast(ca.x + cb.x + pa.x + bv.x);
                res.y = tanh_fast(ca.y + cb.y + pa.y + bv.y);
                res.z = tanh_fast(ca.z + cb.z + pa.z + bv.z);
                res.w = tanh_fast(ca.w + cb.w + pa.w + bv.w);
                cand4[idx] = res;
            }
        }
        grid_bar(target, nblk);

        // ---- phase C: mem update (all blocks, float4) ----
        {
            const float4* hb4 = (const float4*)(hs + (size_t)t*BATCH*HDIM);
            const float4* cand4 = (const float4*)g_cand;
            float4* mem4 = (float4*)g_mem;
            const int total = ROWS * 75;
            for (int idx = blockIdx.x*NTHREADS + tid; idx < total;
                 idx += nblk*NTHREADS) {
                int r  = idx / 75;
                int jq = idx - r*75;
                int b  = r / MCELLS;
                float owv = g_ow[r], iv = g_indv[r];
                float coef = 1.f - owv - iv;
                float4 cd = cand4[idx];
                float4 h  = hb4[b*75 + jq];
                float4 mo = mem4[idx];
                float4 res;
                res.x = owv*h.x + coef*mo.x + iv*cd.x;
                res.y = owv*h.y + coef*mo.y + iv*cd.y;
                res.z = owv*h.z + coef*mo.z + iv*cd.z;
                res.w = owv*h.w + coef*mo.w + iv*cd.w;
                mem4[idx] = res;
            }
        }
        grid_bar(target, nblk);
    }
}

extern "C" void kernel_launch(void* const* d_in, const int* in_sizes, int n_in,
                              void* d_out, int out_size) {
    const float* hs   = (const float*)d_in[0];
    const float* mask = (const float*)d_in[1];
    const float* We1  = (const float*)d_in[2];
    const float* be1  = (const float*)d_in[3];
    const float* We2  = (const float*)d_in[4];
    const float* be2  = (const float*)d_in[5];
    const float* Ws1  = (const float*)d_in[6];
    const float* bs1  = (const float*)d_in[7];
    const float* Ws2  = (const float*)d_in[8];
    const float* bs2  = (const float*)d_in[9];
    const float* Wu   = (const float*)d_in[10];
    const float* bu   = (const float*)d_in[11];
    float* out = (float*)d_out;

    const int smemsz = (int)sizeof(SmemT);
    cudaFuncSetAttribute(k_persist, cudaFuncAttributeMaxDynamicSharedMemorySize,
                         smemsz);

    int smcount = 148;
    cudaDeviceGetAttribute(&smcount, cudaDevAttrMultiProcessorCount, 0);
    int maxb = 1;
    cudaOccupancyMaxActiveBlocksPerMultiprocessor(&maxb, k_persist, NTHREADS,
                                                  smemsz);
    if (maxb > 2) maxb = 2;
    if (maxb < 1) maxb = 1;
    int nblk = maxb * smcount;

    void *pmem, *pusg, *pcnt, *pjob, *ppc;
    cudaGetSymbolAddress(&pmem, g_mem);
    cudaGetSymbolAddress(&pusg, g_usage);
    cudaGetSymbolAddress(&pcnt, g_count);
    cudaGetSymbolAddress(&pjob, g_jobctr);
    cudaGetSymbolAddress(&ppc,  g_pctr);
    cudaMemsetAsync(pmem, 0, sizeof(float)*(size_t)RH);
    cudaMemsetAsync(pusg, 0, sizeof(float)*(size_t)ROWS);
    cudaMemsetAsync(pcnt, 0, sizeof(unsigned));
    cudaMemsetAsync(ppc,  0, sizeof(unsigned));
    cudaMemsetAsync(pjob, 0, sizeof(unsigned)*T_STEPS);

    k_persist<<<nblk, NTHREADS, smemsz>>>(hs, mask, We1, be1, We2, be2,
                                          Ws1, bs1, Ws2, bs2, Wu, bu, out, nblk);
}

// round 15
// speedup vs baseline: 1.1954x; 1.1954x over previous
#include <cuda_runtime.h>
#include <cuda_bf16.h>
#include <math.h>

// ---------------- problem constants ----------------
#define T_STEPS 512
#define BATCH   128
#define HDIM    300
#define MCELLS  20
#define ROWS    (BATCH*MCELLS)   // 2560
#define DECAY   0.98f
#define EPS_V   1e-8f

#define NTHREADS 256
#define NJOBS    300    // 3 matrices * 20rt * 5ct, full K per job
#define PJOBS    (T_STEPS*15)   // one-time P precompute jobs
#define NSTAGE   19     // ceil(304/16) k16-stages, kg>=300 zero-padded
#define RH       (ROWS*HDIM)
#define PSZ      (BATCH*900)
// padded planar weight tables: 3 mem matrices 160 pairs x 320 cols, P 160 x 960
#define WB_MEMSZ  51200          // 160*320 per mem matrix
#define WB_POFF   153600         // 3*51200
#define WBTOT     307200         // + 160*960

// 1 = JAX >= 0.4.30 default (threefry_partitionable)
#define THREEFRY_PARTITIONABLE 1

// ---------------- device state (no allocation anywhere) ----------------
__device__ float g_mem[RH];             // (B,M,H)
__device__ float g_usage[ROWS];         // (B,M)
__device__ float g_HP [RH];             // mem@Ws1[0:300]       (full K)
__device__ float g_HP2[RH];             // (h*mem)@Ws1[600:900] (full K)
__device__ float g_CP [RH];             // mem@Wu[300:600]      (full K)
__device__ float g_Pall[(size_t)T_STEPS*PSZ];  // h_t@[We1|Ws1mid|Wu0]+biases
__device__ float g_cand[RH];            // tanh(CP + P6)
__device__ float g_ow[ROWS];
__device__ float g_indv[ROWS];
__device__ unsigned g_WBh[WBTOT];       // hi bf16-pairs (padded, planar)
__device__ unsigned g_WBl[WBTOT];       // lo bf16-pairs
__device__ float g_bias900[960];        // [be1 | bs1 | bu] (padded)
__device__ unsigned g_count;            // grid-barrier counter
__device__ unsigned g_pctr;             // one-time P job counter
__device__ unsigned g_jobctr[T_STEPS];  // per-step dynamic job counters

// ---------------- dynamic smem tile buffers ----------------
// row stride 24 bf16 (48 B): 16 data + 8 pad -> ldmatrix conflict-free.
struct SmemT {
    unsigned short SAh[2][128][24];
    unsigned short SAl[2][128][24];
    unsigned short SBh[2][64][24];
    unsigned short SBl[2][64][24];
};

// ---------------- software grid barrier ----------------
__device__ __forceinline__ void grid_bar(unsigned &target, int nblk) {
    __syncthreads();
    if (threadIdx.x == 0) {
        target += (unsigned)nblk;
        __threadfence();
        atomicAdd(&g_count, 1u);
        volatile unsigned* p = &g_count;
        while (*p < target) { }
        __threadfence();
    }
    __syncthreads();
}

// ---------------- JAX threefry-2x32-20 noise ----------------
__device__ __forceinline__ void tf_round(unsigned &x0, unsigned &x1, int r) {
    x0 += x1;
    x1 = (x1 << r) | (x1 >> (32 - r));
    x1 ^= x0;
}
__device__ __forceinline__ void threefry2x32(unsigned c0, unsigned c1,
                                             unsigned &o0, unsigned &o1) {
    const unsigned k0 = 0u, k1 = 42u, k2 = 0x1BD11BDAu ^ 0u ^ 42u;
    unsigned x0 = c0 + k0, x1 = c1 + k1;
    tf_round(x0,x1,13); tf_round(x0,x1,15); tf_round(x0,x1,26); tf_round(x0,x1,6);
    x0 += k1; x1 += k2 + 1u;
    tf_round(x0,x1,17); tf_round(x0,x1,29); tf_round(x0,x1,16); tf_round(x0,x1,24);
    x0 += k2; x1 += k0 + 2u;
    tf_round(x0,x1,13); tf_round(x0,x1,15); tf_round(x0,x1,26); tf_round(x0,x1,6);
    x0 += k0; x1 += k1 + 3u;
    tf_round(x0,x1,17); tf_round(x0,x1,29); tf_round(x0,x1,16); tf_round(x0,x1,24);
    x0 += k1; x1 += k2 + 4u;
    tf_round(x0,x1,13); tf_round(x0,x1,15); tf_round(x0,x1,26); tf_round(x0,x1,6);
    x0 += k2; x1 += k0 + 5u;
    o0 = x0; o1 = x1;
}
__device__ __forceinline__ float jax_noise(unsigned i) {
    unsigned bits;
#if THREEFRY_PARTITIONABLE
    unsigned o0, o1;
    threefry2x32(0u, i, o0, o1);
    bits = o0 ^ o1;
#else
    const unsigned half = (unsigned)(T_STEPS*BATCH*MCELLS) / 2u;
    unsigned o0, o1;
    if (i < half) { threefry2x32(i, i + half, o0, o1); bits = o0; }
    else          { threefry2x32(i - half, i, o0, o1); bits = o1; }
#endif
    float f = __uint_as_float((bits >> 9) | 0x3f800000u) - 1.0f;
    float u = __fadd_rn(__fmul_rn(f, 0.99f), 0.01f);
    return fmaxf(0.01f, u);
}

// ---------------- warp reductions ----------------
__device__ __forceinline__ float warpSum(float v) {
#pragma unroll
    for (int o = 16; o; o >>= 1) v += __shfl_xor_sync(0xffffffffu, v, o);
    return v;
}
__device__ __forceinline__ float warpMax(float v) {
#pragma unroll
    for (int o = 16; o; o >>= 1) v = fmaxf(v, __shfl_xor_sync(0xffffffffu, v, o));
    return v;
}

// fast tanh: abs err ~1e-6; __expf(inf)->inf gives exact saturation
__device__ __forceinline__ float tanh_fast(float x) {
    float ax = fabsf(x);
    float e  = __expf(2.0f * ax);
    float r  = 1.0f - __fdividef(2.0f, e + 1.0f);
    return copysignf(r, x);
}

// ---------------- bf16 split helpers ----------------
__device__ __forceinline__ unsigned pack_bf16x2(float e, float o) {
    unsigned r;
    asm("cvt.rn.bf16x2.f32 %0, %1, %2;" : "=r"(r) : "f"(o), "f"(e));
    return r;
}
__device__ __forceinline__ void bsplit(float x, float &hf, float &lf) {
    __nv_bfloat16 h = __float2bfloat16(x);
    hf = __bfloat162float(h);
    lf = x - hf;
}
__device__ __forceinline__ unsigned smem_u32(const void* p) {
    return (unsigned)__cvta_generic_to_shared(p);
}
__device__ __forceinline__ void ldsm4(unsigned r[4], unsigned addr) {
    asm volatile("ldmatrix.sync.aligned.m8n8.x4.shared.b16 {%0,%1,%2,%3}, [%4];"
        : "=r"(r[0]), "=r"(r[1]), "=r"(r[2]), "=r"(r[3]) : "r"(addr));
}
__device__ __forceinline__ void mma_bf16(float c[4],
    unsigned a0, unsigned a1, unsigned a2, unsigned a3,
    unsigned b0, unsigned b1)
{
    asm("mma.sync.aligned.m16n8k16.row.col.f32.bf16.bf16.f32 "
        "{%0,%1,%2,%3}, {%4,%5,%6,%7}, {%8,%9}, {%0,%1,%2,%3};"
        : "+f"(c[0]), "+f"(c[1]), "+f"(c[2]), "+f"(c[3])
        : "r"(a0), "r"(a1), "r"(a2), "r"(a3), "r"(b0), "r"(b1));
}

// ---------------- shared GEMM core (BM=128, BN=64, BK=16, bf16 hi/lo 3-term) ----
// Full K (19 stages). B from padded planar tables, predicate-free LDG+STS.
// bias: optional per-column add in epilogue (for P jobs).
__device__ __forceinline__ void gemm_core(
    const float* aRow0, const float* aRow1,
    const float* h0, const float* h1, bool domul,
    const unsigned* __restrict__ whcol, const unsigned* __restrict__ wlcol,
    int wstride,
    float* dst, int ncols, int c0, const float* __restrict__ bias, SmemT* sm)
{
    const int tid = threadIdx.x;
    const int ar0 = tid >> 2, aq4 = (tid & 3) * 4;  // A: rows ar0/ar0+64, k-quad
    const int bn = tid & 63, bp = tid >> 6;         // B: col, pair-group

    const int warp = tid >> 5, lane = tid & 31;
    const int m0 = (warp >> 1) * 32;
    const int n0 = (warp & 1) * 32;
    const int lg = lane >> 2, lt = lane & 3;

    // ldmatrix lane-dependent byte offsets (row stride 24 bf16 = 48 B)
    const int lrowA = (lane & 7) + ((lane & 8) ? 8 : 0);
    const int lkA   = (lane & 16) ? 8 : 0;
    unsigned aoff[2];
#pragma unroll
    for (int mi = 0; mi < 2; mi++)
        aoff[mi] = (unsigned)(((m0 + mi*16 + lrowA) * 24 + lkA) * 2);
    const int lrowB = (lane & 7) + ((lane & 16) ? 8 : 0);
    const int lkB   = (lane & 8) ? 8 : 0;
    unsigned boff[2];
#pragma unroll
    for (int nip = 0; nip < 2; nip++)
        boff[nip] = (unsigned)(((n0 + nip*16 + lrowB) * 24 + lkB) * 2);

    unsigned baseSAh[2] = { smem_u32(&sm->SAh[0][0][0]), smem_u32(&sm->SAh[1][0][0]) };
    unsigned baseSAl[2] = { smem_u32(&sm->SAl[0][0][0]), smem_u32(&sm->SAl[1][0][0]) };
    unsigned baseSBh[2] = { smem_u32(&sm->SBh[0][0][0]), smem_u32(&sm->SBh[1][0][0]) };
    unsigned baseSBl[2] = { smem_u32(&sm->SBl[0][0][0]), smem_u32(&sm->SBl[1][0][0]) };

    float c[2][4][4];
#pragma unroll
    for (int mi = 0; mi < 2; mi++)
#pragma unroll
        for (int ni = 0; ni < 4; ni++)
#pragma unroll
            for (int q = 0; q < 4; q++) c[mi][ni][q] = 0.f;

    float4 ra0, ra1;
    unsigned rbh0, rbh1, rbl0, rbl1;
    auto ldStage = [&](int s) {
        int kg = s*16 + aq4;
        if (kg < 300) {
            ra0 = *(const float4*)(aRow0 + kg);
            ra1 = *(const float4*)(aRow1 + kg);
            if (domul) {
                float4 f0 = *(const float4*)(h0 + kg);
                float4 f1 = *(const float4*)(h1 + kg);
                ra0.x *= f0.x; ra0.y *= f0.y; ra0.z *= f0.z; ra0.w *= f0.w;
                ra1.x *= f1.x; ra1.y *= f1.y; ra1.z *= f1.z; ra1.w *= f1.w;
            }
        } else {
            ra0 = make_float4(0.f,0.f,0.f,0.f);
            ra1 = make_float4(0.f,0.f,0.f,0.f);
        }
        size_t p0 = (size_t)(s*8 + bp) * wstride;
        rbh0 = whcol[p0];
        rbh1 = whcol[p0 + 4*(size_t)wstride];
        rbl0 = wlcol[p0];
        rbl1 = wlcol[p0 + 4*(size_t)wstride];
    };
    auto stStage = [&](int buf) {
        float hx,lx,hy,ly,hz,lz,hw,lw;
        bsplit(ra0.x,hx,lx); bsplit(ra0.y,hy,ly);
        bsplit(ra0.z,hz,lz); bsplit(ra0.w,hw,lw);
        *(uint2*)&sm->SAh[buf][ar0][aq4] =
            make_uint2(pack_bf16x2(hx,hy), pack_bf16x2(hz,hw));
        *(uint2*)&sm->SAl[buf][ar0][aq4] =
            make_uint2(pack_bf16x2(lx,ly), pack_bf16x2(lz,lw));
        bsplit(ra1.x,hx,lx); bsplit(ra1.y,hy,ly);
        bsplit(ra1.z,hz,lz); bsplit(ra1.w,hw,lw);
        *(uint2*)&sm->SAh[buf][ar0+64][aq4] =
            make_uint2(pack_bf16x2(hx,hy), pack_bf16x2(hz,hw));
        *(uint2*)&sm->SAl[buf][ar0+64][aq4] =
            make_uint2(pack_bf16x2(lx,ly), pack_bf16x2(lz,lw));
        *(unsigned*)&sm->SBh[buf][bn][2*bp]     = rbh0;
        *(unsigned*)&sm->SBl[buf][bn][2*bp]     = rbl0;
        *(unsigned*)&sm->SBh[buf][bn][2*bp + 8] = rbh1;
        *(unsigned*)&sm->SBl[buf][bn][2*bp + 8] = rbl1;
    };

    ldStage(0);
    stStage(0);
    __syncthreads();

    for (int s = 0; s < NSTAGE; s++) {
        int cur = s & 1;
        bool more = (s + 1 < NSTAGE);
        if (more) ldStage(s + 1);   // LDG prefetch overlaps MMA

        unsigned Ah[2][4], Al[2][4], Bh[2][4], Bl[2][4];
#pragma unroll
        for (int mi = 0; mi < 2; mi++) {
            ldsm4(Ah[mi], baseSAh[cur] + aoff[mi]);
            ldsm4(Al[mi], baseSAl[cur] + aoff[mi]);
        }
#pragma unroll
        for (int nip = 0; nip < 2; nip++) {
            ldsm4(Bh[nip], baseSBh[cur] + boff[nip]);
            ldsm4(Bl[nip], baseSBl[cur] + boff[nip]);
        }
#pragma unroll
        for (int mi = 0; mi < 2; mi++)
#pragma unroll
            for (int ni = 0; ni < 4; ni++) {
                int nip = ni >> 1, sel = (ni & 1) * 2;
                unsigned bh0 = Bh[nip][sel], bh1 = Bh[nip][sel+1];
                unsigned bl0 = Bl[nip][sel], bl1 = Bl[nip][sel+1];
                mma_bf16(c[mi][ni], Ah[mi][0], Ah[mi][1], Ah[mi][2], Ah[mi][3],
                         bh0, bh1);
                mma_bf16(c[mi][ni], Ah[mi][0], Ah[mi][1], Ah[mi][2], Ah[mi][3],
                         bl0, bl1);
                mma_bf16(c[mi][ni], Al[mi][0], Al[mi][1], Al[mi][2], Al[mi][3],
                         bh0, bh1);
            }

        if (more) stA: stStage(cur ^ 1);
        __syncthreads();
    }

#pragma unroll
    for (int mi = 0; mi < 2; mi++)
#pragma unroll
        for (int ni = 0; ni < 4; ni++) {
            int row = m0 + mi*16 + lg;
            int col = c0 + n0 + ni*8 + 2*lt;
            float v0 = c[mi][ni][0], v1 = c[mi][ni][1];
            float v2 = c[mi][ni][2], v3 = c[mi][ni][3];
            if (bias) {
                float b0 = bias[col], b1 = bias[col + 1];
                v0 += b0; v2 += b0; v1 += b1; v3 += b1;
            }
            if (col < ncols) {
                dst[row*ncols + col]     = v0;
                dst[(row+8)*ncols + col] = v2;
            }
            if (col + 1 < ncols) {
                dst[row*ncols + col + 1]     = v1;
                dst[(row+8)*ncols + col + 1] = v3;
            }
        }
}

// ---------------- per-step GEMM job (mem-dependent matrices only) ----------------
// 300 jobs: mtype=job/100 (0=HP 1=HP2 2=CP), e=job%100: r0=(e/5)*128, c0=(e%5)*64.
__device__ __forceinline__ void gemm_job(
    int job, int t, const float* __restrict__ hs, SmemT* sm)
{
    const int tid = threadIdx.x;
    const float* hbase = hs + (size_t)t * BATCH * HDIM;

    const int mtype = job / 100;
    int e = job % 100;
    const int r0 = (e / 5) * 128, c0 = (e % 5) * 64;

    const int ar0 = tid >> 2;
    const float* aRow0 = g_mem + (r0 + ar0) * HDIM;
    const float* aRow1 = g_mem + (r0 + ar0 + 64) * HDIM;
    const float* h0 = hbase + ((r0 + ar0) / MCELLS) * HDIM;
    const float* h1 = hbase + ((r0 + ar0 + 64) / MCELLS) * HDIM;

    const int jg = c0 + (tid & 63);
    const unsigned* whcol = g_WBh + mtype * WB_MEMSZ + jg;
    const unsigned* wlcol = g_WBl + mtype * WB_MEMSZ + jg;

    float* dstbase = (mtype == 0) ? g_HP : (mtype == 1) ? g_HP2 : g_CP;

    gemm_core(aRow0, aRow1, h0, h1, (mtype == 1), whcol, wlcol, 320,
              dstbase + r0*300, 300, c0, (const float*)0, sm);
}

// ---------------- one-time P GEMM job (biases folded in epilogue) -------------
__device__ __forceinline__ void pgemm_job(
    int job, const float* __restrict__ hs, SmemT* sm)
{
    const int tid = threadIdx.x;
    const int t = job / 15;
    const int c0 = (job % 15) * 64;
    const float* hbase = hs + (size_t)t * BATCH * HDIM;

    const int ar0 = tid >> 2;
    const float* aRow0 = hbase + ar0 * HDIM;
    const float* aRow1 = hbase + (ar0 + 64) * HDIM;

    const int jg = c0 + (tid & 63);
    const unsigned* whcol = g_WBh + WB_POFF + jg;
    const unsigned* wlcol = g_WBl + WB_POFF + jg;

    gemm_core(aRow0, aRow1, (const float*)0, (const float*)0, false,
              whcol, wlcol, 960,
              g_Pall + (size_t)t*PSZ, 900, c0, g_bias900, sm);
}

// ---------------- gating job (block handles batch b) ----------------
__device__ __forceinline__ void gate_job(
    int b, int t,
    const float* __restrict__ mask,
    const float* __restrict__ We2, const float* __restrict__ be2,
    const float* __restrict__ Ws2, const float* __restrict__ bs2,
    const float* __restrict__ Ws1,
    float* __restrict__ out,
    float (&s_sim)[MCELLS], float (&s_usage)[MCELLS],
    float (&s_red)[8], float &s_ent)
{
    const int tid = threadIdx.x;
    const int warp = tid >> 5, lane = tid & 31;

    const float* P = g_Pall + (size_t)t*PSZ + b*900;   // biases pre-folded
    const float* wu_row = Ws1 + 900*300;

    if (tid < MCELLS) s_usage[tid] = g_usage[b*MCELLS + tid];
    __syncthreads();

    // ---- entity prob (be1 folded into P) ----
    float acc = 0.f;
    for (int j = tid; j < 300; j += NTHREADS)
        acc += fmaxf(P[j], 0.f) * We2[j];
    acc = warpSum(acc);
    if (lane == 0) s_red[warp] = acc;
    __syncthreads();
    if (tid == 0) {
        float s = 0.f;
        for (int w = 0; w < 8; w++) s += s_red[w];
        float score = s + be2[0];
        float sig = 1.f / (1.f + expf(-score));
        s_ent = sig * mask[(size_t)t*BATCH + b];
    }

    // ---- sim[m] (bs1 folded into P[300:600]) ----
    for (int m = warp; m < MCELLS; m += 8) {
        float u = s_usage[m];
        const int ro = (b*MCELLS + m)*300;
        float a = 0.f;
        for (int j = lane; j < 300; j += 32) {
            float pre = g_HP[ro+j] + g_HP2[ro+j] + P[300 + j] + u*wu_row[j];
            a += fmaxf(pre, 0.f) * Ws2[j];
        }
        a = warpSum(a);
        if (lane == 0) s_sim[m] = a + bs2[0];
    }
    __syncthreads();

    // ---- gating (warp 0; lane = slot 0..20) ----
    if (warp == 0) {
        const unsigned FULL = 0xffffffffu;
        const int m = lane;
        const float NEG_INF = -INFINITY;
        float usg  = (m < MCELLS) ? s_usage[m] : 0.f;
        float simv = (m < MCELLS) ? s_sim[m]   : 0.f;

        float comb;
        if (m < MCELLS)       comb = (usg > 0.f) ? simv : -10000.f;
        else if (m == MCELLS) comb = 0.f;
        else                  comb = NEG_INF;
        float mx   = warpMax(comb);
        float ex   = (m <= MCELLS) ? expf(comb - mx) : 0.f;
        float esum = warpSum(ex);
        float prob = ex / esum;
        float mult = (m < MCELLS) ? ((usg > 0.f) ? 1.f : 0.f)
                                  : ((m == MCELLS) ? 1.f : 0.f);
        float maskedp = prob * mult;
        float msum = warpSum(maskedp);
        float nrm  = maskedp / (msum + EPS_V);
        float co   = s_ent * nrm;
        float ow_base = __shfl_sync(FULL, co, MCELLS);
        float indv = (m < MCELLS) ? co : 0.f;

        float s2  = (m < MCELLS) ? simv : NEG_INF;
        float mx2 = warpMax(s2);
        float e2  = (m < MCELLS) ? expf(simv - mx2) : 0.f;
        float es2 = warpSum(e2);
        float nsim = e2 / es2;

        float ow_score = (m < MCELLS)
            ? ((usg == 0.f ? nsim * 100000.f : 0.f) + (1.f - usg))
            : NEG_INF;
        float maxv = warpMax(ow_score);
        float nz   = (m < MCELLS && ow_score == maxv)
            ? jax_noise((unsigned)(((size_t)t*BATCH + b)*MCELLS + m)) : 0.f;
        float nzmax = warpMax(nz);
        unsigned ballot = __ballot_sync(FULL, (m < MCELLS) && (nz == nzmax));
        int idx = __ffs(ballot) - 1;

        float ow = (m == idx) ? ow_base : 0.f;
        float nu = fminf(1.f, ow + indv + DECAY * usg);

        float* out_ent = out;
        float* out_usg = out + (size_t)T_STEPS*BATCH;
        float* out_crf = out_usg + (size_t)T_STEPS*BATCH*MCELLS;
        float* out_ow  = out_crf + (size_t)T_STEPS*BATCH*MCELLS;
        if (m < MCELLS) {
            g_ow[b*MCELLS + m]    = ow;
            g_indv[b*MCELLS + m]  = indv;
            g_usage[b*MCELLS + m] = nu;
            size_t o = ((size_t)t*BATCH + b)*MCELLS + m;
            out_usg[o] = nu;
            out_crf[o] = indv * (1.f - EPS_V) + EPS_V;
            out_ow[o]  = ow   * (1.f - EPS_V) + EPS_V;
        }
        if (m == 0)
            out_ent[(size_t)t*BATCH + b] = s_ent * (1.f - EPS_V) + EPS_V;
    }
}

// ---------------- persistent kernel ----------------
__global__ __launch_bounds__(NTHREADS, 2) void k_persist(
    const float* __restrict__ hs, const float* __restrict__ mask,
    const float* __restrict__ We1, const float* __restrict__ be1,
    const float* __restrict__ We2, const float* __restrict__ be2,
    const float* __restrict__ Ws1, const float* __restrict__ bs1,
    const float* __restrict__ Ws2, const float* __restrict__ bs2,
    const float* __restrict__ Wu,  const float* __restrict__ bu,
    float* __restrict__ out, int nblk)
{
    extern __shared__ char smem_raw[];
    SmemT* sm = (SmemT*)smem_raw;

    __shared__ float s_sim[MCELLS], s_usage[MCELLS];
    __shared__ float s_red[8];
    __shared__ float s_ent;
    __shared__ int s_job;

    const int tid = threadIdx.x;
    unsigned target = 0;

    // ---- one-time: bias vector + padded planar bf16 split weight tables ----
    for (int j = blockIdx.x*NTHREADS + tid; j < 960; j += nblk*NTHREADS) {
        float v = 0.f;
        if (j < 300)      v = be1[j];
        else if (j < 600) v = bs1[j - 300];
        else if (j < 900) v = bu[j - 600];
        g_bias900[j] = v;
    }
    for (int idx = blockIdx.x*NTHREADS + tid; idx < WBTOT; idx += nblk*NTHREADS) {
        float v0 = 0.f, v1 = 0.f;
        if (idx < WB_POFF) {
            int mtype = idx / WB_MEMSZ;
            int e = idx % WB_MEMSZ;
            int p = e / 320, j = e % 320;
            int k0 = 2*p, k1 = 2*p + 1;
            if (j < 300 && k0 < 300) {
                if (mtype == 0)      { v0 = Ws1[k0*300 + j];
                                       if (k1 < 300) v1 = Ws1[k1*300 + j]; }
                else if (mtype == 1) { v0 = Ws1[(600+k0)*300 + j];
                                       if (k1 < 300) v1 = Ws1[(600+k1)*300 + j]; }
                else                 { v0 = Wu[(300+k0)*300 + j];
                                       if (k1 < 300) v1 = Wu[(300+k1)*300 + j]; }
            }
        } else {
            int e = idx - WB_POFF;
            int p = e / 960, j = e % 960;
            int k0 = 2*p, k1 = 2*p + 1;
            if (j < 900 && k0 < 300) {
                int role = j / 300, jc = j - role*300;
                if (role == 0)      { v0 = We1[k0*300 + jc];
                                      if (k1 < 300) v1 = We1[k1*300 + jc]; }
                else if (role == 1) { v0 = Ws1[(300+k0)*300 + jc];
                                      if (k1 < 300) v1 = Ws1[(300+k1)*300 + jc]; }
                else                { v0 = Wu[k0*300 + jc];
                                      if (k1 < 300) v1 = Wu[k1*300 + jc]; }
            }
        }
        float h0,l0,h1,l1;
        bsplit(v0, h0, l0);
        bsplit(v1, h1, l1);
        g_WBh[idx] = pack_bf16x2(h0, h1);
        g_WBl[idx] = pack_bf16x2(l0, l1);
    }
    grid_bar(target, nblk);

    // ---- one-time: precompute P for ALL steps (h-only GEMM, bias folded) ----
    for (;;) {
        if (tid == 0) s_job = (int)atomicAdd(&g_pctr, 1u);
        __syncthreads();
        int job = s_job;
        __syncthreads();
        if (job >= PJOBS) break;
        pgemm_job(job, hs, sm);
    }
    grid_bar(target, nblk);

    for (int t = 0; t < T_STEPS; t++) {
        // ---- phase A: mem-dependent GEMMs (dynamic, tensor cores) ----
        for (;;) {
            if (tid == 0) s_job = (int)atomicAdd(&g_jobctr[t], 1u);
            __syncthreads();
            int job = s_job;
            __syncthreads();
            if (job >= NJOBS) break;
            gemm_job(job, t, hs, sm);
        }
        grid_bar(target, nblk);

        // ---- phase B: gate (blocks 0..127) || cand precompute (rest) ----
        if (blockIdx.x < BATCH) {
            gate_job(blockIdx.x, t, mask, We2, be2, Ws2, bs2,
                     Ws1, out, s_sim, s_usage, s_red, s_ent);
        } else {
            const float4* CP4 = (const float4*)g_CP;
            const float4* Pt4 = (const float4*)(g_Pall + (size_t)t*PSZ);
            float4* cand4 = (float4*)g_cand;
            const int total = ROWS * 75;
            const int nb = nblk - BATCH;
            for (int idx = (blockIdx.x - BATCH)*NTHREADS + tid; idx < total;
                 idx += nb*NTHREADS) {
                int r  = idx / 75;
                int jq = idx - r*75;
                int b  = r / MCELLS;
                float4 ca = CP4[idx];
                float4 pa = Pt4[b*225 + 150 + jq];   // bu folded
                float4 res;
                res.x = tanh_fast(ca.x + pa.x);
                res.y = tanh_fast(ca.y + pa.y);
                res.z = tanh_fast(ca.z + pa.z);
                res.w = tanh_fast(ca.w + pa.w);
                cand4[idx] = res;
            }
        }
        grid_bar(target, nblk);

        // ---- phase C: mem update (all blocks, float4) ----
        {
            const float4* hb4 = (const float4*)(hs + (size_t)t*BATCH*HDIM);
            const float4* cand4 = (const float4*)g_cand;
            float4* mem4 = (float4*)g_mem;
            const int total = ROWS * 75;
            for (int idx = blockIdx.x*NTHREADS + tid; idx < total;
                 idx += nblk*NTHREADS) {
                int r  = idx / 75;
                int jq = idx - r*75;
                int b  = r / MCELLS;
                float owv = g_ow[r], iv = g_indv[r];
                float coef = 1.f - owv - iv;
                float4 cd = cand4[idx];
                float4 h  = hb4[b*75 + jq];
                float4 mo = mem4[idx];
                float4 res;
                res.x = owv*h.x + coef*mo.x + iv*cd.x;
                res.y = owv*h.y + coef*mo.y + iv*cd.y;
                res.z = owv*h.z + coef*mo.z + iv*cd.z;
                res.w = owv*h.w + coef*mo.w + iv*cd.w;
                mem4[idx] = res;
            }
        }
        grid_bar(target, nblk);
    }
}

extern "C" void kernel_launch(void* const* d_in, const int* in_sizes, int n_in,
                              void* d_out, int out_size) {
    const float* hs   = (const float*)d_in[0];
    const float* mask = (const float*)d_in[1];
    const float* We1  = (const float*)d_in[2];
    const float* be1  = (const float*)d_in[3];
    const float* We2  = (const float*)d_in[4];
    const float* be2  = (const float*)d_in[5];
    const float* Ws1  = (const float*)d_in[6];
    const float* bs1  = (const float*)d_in[7];
    const float* Ws2  = (const float*)d_in[8];
    const float* bs2  = (const float*)d_in[9];
    const float* Wu   = (const float*)d_in[10];
    const float* bu   = (const float*)d_in[11];
    float* out = (float*)d_out;

    const int smemsz = (int)sizeof(SmemT);
    cudaFuncSetAttribute(k_persist, cudaFuncAttributeMaxDynamicSharedMemorySize,
                         smemsz);

    int smcount = 148;
    cudaDeviceGetAttribute(&smcount, cudaDevAttrMultiProcessorCount, 0);
    int maxb = 1;
    cudaOccupancyMaxActiveBlocksPerMultiprocessor(&maxb, k_persist, NTHREADS,
                                                  smemsz);
    if (maxb > 2) maxb = 2;
    if (maxb < 1) maxb = 1;
    int nblk = maxb * smcount;

    void *pmem, *pusg, *pcnt, *pjob, *ppc;
    cudaGetSymbolAddress(&pmem, g_mem);
    cudaGetSymbolAddress(&pusg, g_usage);
    cudaGetSymbolAddress(&pcnt, g_count);
    cudaGetSymbolAddress(&pjob, g_jobctr);
    cudaGetSymbolAddress(&ppc,  g_pctr);
    cudaMemsetAsync(pmem, 0, sizeof(float)*(size_t)RH);
    cudaMemsetAsync(pusg, 0, sizeof(float)*(size_t)ROWS);
    cudaMemsetAsync(pcnt, 0, sizeof(unsigned));
    cudaMemsetAsync(ppc,  0, sizeof(unsigned));
    cudaMemsetAsync(pjob, 0, sizeof(unsigned)*T_STEPS);

    k_persist<<<nblk, NTHREADS, smemsz>>>(hs, mask, We1, be1, We2, be2,
                                          Ws1, bs1, Ws2, bs2, Wu, bu, out, nblk);
}

// round 16
// speedup vs baseline: 1.3688x; 1.1450x over previous
#include <cuda_runtime.h>
#include <cuda_bf16.h>
#include <math.h>

// ---------------- problem constants ----------------
#define T_STEPS 512
#define BATCH   128
#define HDIM    300
#define MCELLS  20
#define ROWS    (BATCH*MCELLS)   // 2560
#define DECAY   0.98f
#define EPS_V   1e-8f

#define NTHREADS 256
#define NJOBS    300    // 3 matrices * 20rt * 5ct, full K per job
#define PJOBS    (T_STEPS*15)   // one-time P precompute jobs
#define NSTAGE   10     // k32 stages over padded K=320 (pairs 0..159)
#define RH       (ROWS*HDIM)
#define PSZ      (BATCH*900)
#define APITCH   160            // pairs per row in A/B tables (zero-padded >=150)
// col-major padded B tables: 3 mem matrices 320 cols x 160 pairs, P 960 x 160
#define WB_MEMSZ  (320*APITCH)  // 51200 per mem matrix
#define WB_POFF   (3*WB_MEMSZ)  // 153600
#define WBTOT     (WB_POFF + 960*APITCH)
#define HSROWS    (T_STEPS*BATCH)  // 65536

// 1 = JAX >= 0.4.30 default (threefry_partitionable)
#define THREEFRY_PARTITIONABLE 1

// ---------------- device state (no allocation anywhere) ----------------
__device__ float g_mem[RH];             // (B,M,H)
__device__ float g_usage[ROWS];         // (B,M)
__device__ float g_HP [RH];             // mem@Ws1[0:300]
__device__ float g_HP2[RH];             // (h*mem)@Ws1[600:900]
__device__ float g_CP [RH];             // mem@Wu[300:600]
__device__ float g_Pall[(size_t)T_STEPS*PSZ];  // h_t@[We1|Ws1mid|Wu0]+biases
__device__ float g_cand[RH];            // tanh(CP + P6)
__device__ float g_ow[ROWS];
__device__ float g_indv[ROWS];
__device__ unsigned g_WBh[WBTOT];       // B hi bf16-pairs, col-major [col][pair]
__device__ unsigned g_WBl[WBTOT];       // B lo
__device__ unsigned g_AMh[ROWS*APITCH]; // mem split tables   [row][pair]
__device__ unsigned g_AMl[ROWS*APITCH];
__device__ unsigned g_AHh[ROWS*APITCH]; // h*mem split tables
__device__ unsigned g_AHl[ROWS*APITCH];
__device__ unsigned g_HSh[(size_t)HSROWS*APITCH]; // hs split tables (for P jobs)
__device__ unsigned g_HSl[(size_t)HSROWS*APITCH];
__device__ float g_bias900[960];        // [be1 | bs1 | bu] (padded)
__device__ unsigned g_count;            // grid-barrier counter
__device__ unsigned g_pctr;             // one-time P job counter
__device__ unsigned g_jobctr[T_STEPS];  // per-step dynamic job counters

// ---------------- dynamic smem tile buffers ----------------
// [buf][k16-block][row][24 shorts]: 16 data + 8 pad; 48B rows, ldmatrix-friendly
struct SmemT {
    unsigned short SAh[2][2][128][24];
    unsigned short SAl[2][2][128][24];
    unsigned short SBh[2][2][64][24];
    unsigned short SBl[2][2][64][24];
};

// ---------------- software grid barrier ----------------
__device__ __forceinline__ void grid_bar(unsigned &target, int nblk) {
    __syncthreads();
    if (threadIdx.x == 0) {
        target += (unsigned)nblk;
        __threadfence();
        atomicAdd(&g_count, 1u);
        volatile unsigned* p = &g_count;
        while (*p < target) { }
        __threadfence();
    }
    __syncthreads();
}

// ---------------- JAX threefry-2x32-20 noise ----------------
__device__ __forceinline__ void tf_round(unsigned &x0, unsigned &x1, int r) {
    x0 += x1;
    x1 = (x1 << r) | (x1 >> (32 - r));
    x1 ^= x0;
}
__device__ __forceinline__ void threefry2x32(unsigned c0, unsigned c1,
                                             unsigned &o0, unsigned &o1) {
    const unsigned k0 = 0u, k1 = 42u, k2 = 0x1BD11BDAu ^ 0u ^ 42u;
    unsigned x0 = c0 + k0, x1 = c1 + k1;
    tf_round(x0,x1,13); tf_round(x0,x1,15); tf_round(x0,x1,26); tf_round(x0,x1,6);
    x0 += k1; x1 += k2 + 1u;
    tf_round(x0,x1,17); tf_round(x0,x1,29); tf_round(x0,x1,16); tf_round(x0,x1,24);
    x0 += k2; x1 += k0 + 2u;
    tf_round(x0,x1,13); tf_round(x0,x1,15); tf_round(x0,x1,26); tf_round(x0,x1,6);
    x0 += k0; x1 += k1 + 3u;
    tf_round(x0,x1,17); tf_round(x0,x1,29); tf_round(x0,x1,16); tf_round(x0,x1,24);
    x0 += k1; x1 += k2 + 4u;
    tf_round(x0,x1,13); tf_round(x0,x1,15); tf_round(x0,x1,26); tf_round(x0,x1,6);
    x0 += k2; x1 += k0 + 5u;
    o0 = x0; o1 = x1;
}
__device__ __forceinline__ float jax_noise(unsigned i) {
    unsigned bits;
#if THREEFRY_PARTITIONABLE
    unsigned o0, o1;
    threefry2x32(0u, i, o0, o1);
    bits = o0 ^ o1;
#else
    const unsigned half = (unsigned)(T_STEPS*BATCH*MCELLS) / 2u;
    unsigned o0, o1;
    if (i < half) { threefry2x32(i, i + half, o0, o1); bits = o0; }
    else          { threefry2x32(i - half, i, o0, o1); bits = o1; }
#endif
    float f = __uint_as_float((bits >> 9) | 0x3f800000u) - 1.0f;
    float u = __fadd_rn(__fmul_rn(f, 0.99f), 0.01f);
    return fmaxf(0.01f, u);
}

// ---------------- warp reductions ----------------
__device__ __forceinline__ float warpSum(float v) {
#pragma unroll
    for (int o = 16; o; o >>= 1) v += __shfl_xor_sync(0xffffffffu, v, o);
    return v;
}
__device__ __forceinline__ float warpMax(float v) {
#pragma unroll
    for (int o = 16; o; o >>= 1) v = fmaxf(v, __shfl_xor_sync(0xffffffffu, v, o));
    return v;
}

// fast tanh: abs err ~1e-6; __expf(inf)->inf gives exact saturation
__device__ __forceinline__ float tanh_fast(float x) {
    float ax = fabsf(x);
    float e  = __expf(2.0f * ax);
    float r  = 1.0f - __fdividef(2.0f, e + 1.0f);
    return copysignf(r, x);
}

// ---------------- bf16 split helpers ----------------
__device__ __forceinline__ unsigned pack_bf16x2(float e, float o) {
    unsigned r;
    asm("cvt.rn.bf16x2.f32 %0, %1, %2;" : "=r"(r) : "f"(o), "f"(e));
    return r;
}
__device__ __forceinline__ void bsplit(float x, float &hf, float &lf) {
    __nv_bfloat16 h = __float2bfloat16(x);
    hf = __bfloat162float(h);
    lf = x - hf;
}
__device__ __forceinline__ unsigned smem_u32(const void* p) {
    return (unsigned)__cvta_generic_to_shared(p);
}
__device__ __forceinline__ void ldsm4(unsigned r[4], unsigned addr) {
    asm volatile("ldmatrix.sync.aligned.m8n8.x4.shared.b16 {%0,%1,%2,%3}, [%4];"
        : "=r"(r[0]), "=r"(r[1]), "=r"(r[2]), "=r"(r[3]) : "r"(addr));
}
__device__ __forceinline__ void mma_bf16(float c[4],
    unsigned a0, unsigned a1, unsigned a2, unsigned a3,
    unsigned b0, unsigned b1)
{
    asm("mma.sync.aligned.m16n8k16.row.col.f32.bf16.bf16.f32 "
        "{%0,%1,%2,%3}, {%4,%5,%6,%7}, {%8,%9}, {%0,%1,%2,%3};"
        : "+f"(c[0]), "+f"(c[1]), "+f"(c[2]), "+f"(c[3])
        : "r"(a0), "r"(a1), "r"(a2), "r"(a3), "r"(b0), "r"(b1));
}

// ---------------- fast GEMM core (pre-split A/B tables, BM=128/BN=64/BK=32) ----
// Ah/Al: A split tables base + r0*APITCH. Bh/Bl: B tables base + c0*APITCH
// (col-major [col][pair]). Pure uint4 copy staging; zero hot-loop ALU.
__device__ __forceinline__ void gemm_fast(
    const unsigned* __restrict__ Ah, const unsigned* __restrict__ Al,
    const unsigned* __restrict__ Bh, const unsigned* __restrict__ Bl,
    float* dst, int ncols, int c0, const float* __restrict__ bias, SmemT* sm)
{
    const int tid = threadIdx.x;
    const int warp = tid >> 5, lane = tid & 31;
    const int m0 = (warp >> 1) * 32;
    const int n0 = (warp & 1) * 32;
    const int lg = lane >> 2, lt = lane & 3;

    // staging coords: A 512 uint4-slots/plane (2/thread), B 256 (1/thread)
    const int aRow0 = tid >> 2,       aQ0 = tid & 3;
    const int aRow1 = (tid + 256) >> 2, aQ1 = (tid + 256) & 3;
    const int bCol = tid >> 2,        bQ = tid & 3;
    const size_t aOff0 = (size_t)aRow0*APITCH + (aQ0>>1)*8 + (aQ0&1)*4;
    const size_t aOff1 = (size_t)aRow1*APITCH + (aQ1>>1)*8 + (aQ1&1)*4;
    const size_t bOff  = (size_t)bCol*APITCH + (bQ>>1)*8 + (bQ&1)*4;

    // ldmatrix lane-dependent byte offsets (row stride 24 bf16 = 48 B)
    const int lrowA = (lane & 7) + ((lane & 8) ? 8 : 0);
    const int lkA   = (lane & 16) ? 8 : 0;
    unsigned aoff[2];
#pragma unroll
    for (int mi = 0; mi < 2; mi++)
        aoff[mi] = (unsigned)(((m0 + mi*16 + lrowA) * 24 + lkA) * 2);
    const int lrowB = (lane & 7) + ((lane & 16) ? 8 : 0);
    const int lkB   = (lane & 8) ? 8 : 0;
    unsigned boff[2];
#pragma unroll
    for (int nip = 0; nip < 2; nip++)
        boff[nip] = (unsigned)(((n0 + nip*16 + lrowB) * 24 + lkB) * 2);

    unsigned baseSAh[2] = { smem_u32(&sm->SAh[0][0][0][0]), smem_u32(&sm->SAh[1][0][0][0]) };
    unsigned baseSAl[2] = { smem_u32(&sm->SAl[0][0][0][0]), smem_u32(&sm->SAl[1][0][0][0]) };
    unsigned baseSBh[2] = { smem_u32(&sm->SBh[0][0][0][0]), smem_u32(&sm->SBh[1][0][0][0]) };
    unsigned baseSBl[2] = { smem_u32(&sm->SBl[0][0][0][0]), smem_u32(&sm->SBl[1][0][0][0]) };

    float c[2][4][4];
#pragma unroll
    for (int mi = 0; mi < 2; mi++)
#pragma unroll
        for (int ni = 0; ni < 4; ni++)
#pragma unroll
            for (int q = 0; q < 4; q++) c[mi][ni][q] = 0.f;

    uint4 rAh0, rAh1, rAl0, rAl1, rBh, rBl;
    auto ldStage = [&](int s) {
        const size_t kb = (size_t)s * 16;
        rAh0 = *(const uint4*)(Ah + aOff0 + kb);
        rAh1 = *(const uint4*)(Ah + aOff1 + kb);
        rAl0 = *(const uint4*)(Al + aOff0 + kb);
        rAl1 = *(const uint4*)(Al + aOff1 + kb);
        rBh  = *(const uint4*)(Bh + bOff + kb);
        rBl  = *(const uint4*)(Bl + bOff + kb);
    };
    auto stStage = [&](int buf) {
        *(uint4*)&sm->SAh[buf][aQ0>>1][aRow0][(aQ0&1)*8] = rAh0;
        *(uint4*)&sm->SAh[buf][aQ1>>1][aRow1][(aQ1&1)*8] = rAh1;
        *(uint4*)&sm->SAl[buf][aQ0>>1][aRow0][(aQ0&1)*8] = rAl0;
        *(uint4*)&sm->SAl[buf][aQ1>>1][aRow1][(aQ1&1)*8] = rAl1;
        *(uint4*)&sm->SBh[buf][bQ>>1][bCol][(bQ&1)*8] = rBh;
        *(uint4*)&sm->SBl[buf][bQ>>1][bCol][(bQ&1)*8] = rBl;
    };

    ldStage(0);
    stStage(0);
    __syncthreads();

    for (int s = 0; s < NSTAGE; s++) {
        int cur = s & 1;
        bool more = (s + 1 < NSTAGE);
        if (more) ldStage(s + 1);   // LDG prefetch overlaps MMA

#pragma unroll
        for (int kb = 0; kb < 2; kb++) {
            unsigned Ahf[2][4], Alf[2][4], Bhf[2][4], Blf[2][4];
#pragma unroll
            for (int mi = 0; mi < 2; mi++) {
                ldsm4(Ahf[mi], baseSAh[cur] + kb*6144u + aoff[mi]);
                ldsm4(Alf[mi], baseSAl[cur] + kb*6144u + aoff[mi]);
            }
#pragma unroll
            for (int nip = 0; nip < 2; nip++) {
                ldsm4(Bhf[nip], baseSBh[cur] + kb*3072u + boff[nip]);
                ldsm4(Blf[nip], baseSBl[cur] + kb*3072u + boff[nip]);
            }
#pragma unroll
            for (int mi = 0; mi < 2; mi++)
#pragma unroll
                for (int ni = 0; ni < 4; ni++) {
                    int nip = ni >> 1, sel = (ni & 1) * 2;
                    unsigned bh0 = Bhf[nip][sel], bh1 = Bhf[nip][sel+1];
                    unsigned bl0 = Blf[nip][sel], bl1 = Blf[nip][sel+1];
                    mma_bf16(c[mi][ni], Ahf[mi][0], Ahf[mi][1], Ahf[mi][2], Ahf[mi][3],
                             bh0, bh1);
                    mma_bf16(c[mi][ni], Ahf[mi][0], Ahf[mi][1], Ahf[mi][2], Ahf[mi][3],
                             bl0, bl1);
                    mma_bf16(c[mi][ni], Alf[mi][0], Alf[mi][1], Alf[mi][2], Alf[mi][3],
                             bh0, bh1);
                }
        }

        if (more) stStage(cur ^ 1);
        __syncthreads();
    }

#pragma unroll
    for (int mi = 0; mi < 2; mi++)
#pragma unroll
        for (int ni = 0; ni < 4; ni++) {
            int row = m0 + mi*16 + lg;
            int col = c0 + n0 + ni*8 + 2*lt;
            float v0 = c[mi][ni][0], v1 = c[mi][ni][1];
            float v2 = c[mi][ni][2], v3 = c[mi][ni][3];
            if (bias) {
                float b0 = bias[col], b1 = bias[col + 1];
                v0 += b0; v2 += b0; v1 += b1; v3 += b1;
            }
            if (col < ncols) {
                dst[row*ncols + col]     = v0;
                dst[(row+8)*ncols + col] = v2;
            }
            if (col + 1 < ncols) {
                dst[row*ncols + col + 1]     = v1;
                dst[(row+8)*ncols + col + 1] = v3;
            }
        }
}

// ---------------- per-step GEMM job ----------------
// 300 jobs: mtype=job/100 (0=HP 1=HP2 2=CP), e=job%100: r0=(e/5)*128, c0=(e%5)*64.
__device__ __forceinline__ void gemm_job(int job, SmemT* sm)
{
    const int mtype = job / 100;
    int e = job % 100;
    const int r0 = (e / 5) * 128, c0 = (e % 5) * 64;

    const unsigned* Ah = ((mtype == 1) ? g_AHh : g_AMh) + (size_t)r0*APITCH;
    const unsigned* Al = ((mtype == 1) ? g_AHl : g_AMl) + (size_t)r0*APITCH;
    const unsigned* Bh = g_WBh + mtype * WB_MEMSZ + (size_t)c0*APITCH;
    const unsigned* Bl = g_WBl + mtype * WB_MEMSZ + (size_t)c0*APITCH;

    float* dstbase = (mtype == 0) ? g_HP : (mtype == 1) ? g_HP2 : g_CP;
    gemm_fast(Ah, Al, Bh, Bl, dstbase + r0*300, 300, c0, (const float*)0, sm);
}

// ---------------- one-time P GEMM job (biases folded) ----------------
__device__ __forceinline__ void pgemm_job(int job, SmemT* sm)
{
    const int t = job / 15;
    const int c0 = (job % 15) * 64;
    const unsigned* Ah = g_HSh + (size_t)t*128*APITCH;
    const unsigned* Al = g_HSl + (size_t)t*128*APITCH;
    const unsigned* Bh = g_WBh + WB_POFF + (size_t)c0*APITCH;
    const unsigned* Bl = g_WBl + WB_POFF + (size_t)c0*APITCH;
    gemm_fast(Ah, Al, Bh, Bl, g_Pall + (size_t)t*PSZ, 900, c0, g_bias900, sm);
}

// ---------------- gating job (block handles batch b) ----------------
__device__ __forceinline__ void gate_job(
    int b, int t,
    const float* __restrict__ mask,
    const float* __restrict__ We2, const float* __restrict__ be2,
    const float* __restrict__ Ws2, const float* __restrict__ bs2,
    const float* __restrict__ Ws1,
    float* __restrict__ out,
    float (&s_sim)[MCELLS], float (&s_usage)[MCELLS],
    float (&s_red)[8], float &s_ent)
{
    const int tid = threadIdx.x;
    const int warp = tid >> 5, lane = tid & 31;

    const float* P = g_Pall + (size_t)t*PSZ + b*900;   // biases pre-folded
    const float* wu_row = Ws1 + 900*300;

    if (tid < MCELLS) s_usage[tid] = g_usage[b*MCELLS + tid];
    __syncthreads();

    // ---- entity prob (be1 folded into P) ----
    float acc = 0.f;
    for (int j = tid; j < 300; j += NTHREADS)
        acc += fmaxf(P[j], 0.f) * We2[j];
    acc = warpSum(acc);
    if (lane == 0) s_red[warp] = acc;
    __syncthreads();
    if (tid == 0) {
        float s = 0.f;
        for (int w = 0; w < 8; w++) s += s_red[w];
        float score = s + be2[0];
        float sig = 1.f / (1.f + expf(-score));
        s_ent = sig * mask[(size_t)t*BATCH + b];
    }

    // ---- sim[m] (bs1 folded into P[300:600]) ----
    for (int m = warp; m < MCELLS; m += 8) {
        float u = s_usage[m];
        const int ro = (b*MCELLS + m)*300;
        float a = 0.f;
        for (int j = lane; j < 300; j += 32) {
            float pre = g_HP[ro+j] + g_HP2[ro+j] + P[300 + j] + u*wu_row[j];
            a += fmaxf(pre, 0.f) * Ws2[j];
        }
        a = warpSum(a);
        if (lane == 0) s_sim[m] = a + bs2[0];
    }
    __syncthreads();

    // ---- gating (warp 0; lane = slot 0..20) ----
    if (warp == 0) {
        const unsigned FULL = 0xffffffffu;
        const int m = lane;
        const float NEG_INF = -INFINITY;
        float usg  = (m < MCELLS) ? s_usage[m] : 0.f;
        float simv = (m < MCELLS) ? s_sim[m]   : 0.f;

        float comb;
        if (m < MCELLS)       comb = (usg > 0.f) ? simv : -10000.f;
        else if (m == MCELLS) comb = 0.f;
        else                  comb = NEG_INF;
        float mx   = warpMax(comb);
        float ex   = (m <= MCELLS) ? expf(comb - mx) : 0.f;
        float esum = warpSum(ex);
        float prob = ex / esum;
        float mult = (m < MCELLS) ? ((usg > 0.f) ? 1.f : 0.f)
                                  : ((m == MCELLS) ? 1.f : 0.f);
        float maskedp = prob * mult;
        float msum = warpSum(maskedp);
        float nrm  = maskedp / (msum + EPS_V);
        float co   = s_ent * nrm;
        float ow_base = __shfl_sync(FULL, co, MCELLS);
        float indv = (m < MCELLS) ? co : 0.f;

        float s2  = (m < MCELLS) ? simv : NEG_INF;
        float mx2 = warpMax(s2);
        float e2  = (m < MCELLS) ? expf(simv - mx2) : 0.f;
        float es2 = warpSum(e2);
        float nsim = e2 / es2;

        float ow_score = (m < MCELLS)
            ? ((usg == 0.f ? nsim * 100000.f : 0.f) + (1.f - usg))
            : NEG_INF;
        float maxv = warpMax(ow_score);
        float nz   = (m < MCELLS && ow_score == maxv)
            ? jax_noise((unsigned)(((size_t)t*BATCH + b)*MCELLS + m)) : 0.f;
        float nzmax = warpMax(nz);
        unsigned ballot = __ballot_sync(FULL, (m < MCELLS) && (nz == nzmax));
        int idx = __ffs(ballot) - 1;

        float ow = (m == idx) ? ow_base : 0.f;
        float nu = fminf(1.f, ow + indv + DECAY * usg);

        float* out_ent = out;
        float* out_usg = out + (size_t)T_STEPS*BATCH;
        float* out_crf = out_usg + (size_t)T_STEPS*BATCH*MCELLS;
        float* out_ow  = out_crf + (size_t)T_STEPS*BATCH*MCELLS;
        if (m < MCELLS) {
            g_ow[b*MCELLS + m]    = ow;
            g_indv[b*MCELLS + m]  = indv;
            g_usage[b*MCELLS + m] = nu;
            size_t o = ((size_t)t*BATCH + b)*MCELLS + m;
            out_usg[o] = nu;
            out_crf[o] = indv * (1.f - EPS_V) + EPS_V;
            out_ow[o]  = ow   * (1.f - EPS_V) + EPS_V;
        }
        if (m == 0)
            out_ent[(size_t)t*BATCH + b] = s_ent * (1.f - EPS_V) + EPS_V;
    }
}

// ---------------- persistent kernel ----------------
__global__ __launch_bounds__(NTHREADS, 2) void k_persist(
    const float* __restrict__ hs, const float* __restrict__ mask,
    const float* __restrict__ We1, const float* __restrict__ be1,
    const float* __restrict__ We2, const float* __restrict__ be2,
    const float* __restrict__ Ws1, const float* __restrict__ bs1,
    const float* __restrict__ Ws2, const float* __restrict__ bs2,
    const float* __restrict__ Wu,  const float* __restrict__ bu,
    float* __restrict__ out, int nblk)
{
    extern __shared__ char smem_raw[];
    SmemT* sm = (SmemT*)smem_raw;

    __shared__ float s_sim[MCELLS], s_usage[MCELLS];
    __shared__ float s_red[8];
    __shared__ float s_ent;
    __shared__ int s_job;

    const int tid = threadIdx.x;
    unsigned target = 0;

    // ---- one-time: bias vector ----
    for (int j = blockIdx.x*NTHREADS + tid; j < 960; j += nblk*NTHREADS) {
        float v = 0.f;
        if (j < 300)      v = be1[j];
        else if (j < 600) v = bs1[j - 300];
        else if (j < 900) v = bu[j - 600];
        g_bias900[j] = v;
    }
    // ---- one-time: col-major padded B split tables ----
    for (int idx = blockIdx.x*NTHREADS + tid; idx < WBTOT; idx += nblk*NTHREADS) {
        float v0 = 0.f, v1 = 0.f;
        if (idx < WB_POFF) {
            int mtype = idx / WB_MEMSZ;
            int e = idx % WB_MEMSZ;
            int col = e / APITCH, p = e % APITCH;
            int k0 = 2*p, k1 = 2*p + 1;
            if (col < 300 && k0 < 300) {
                if (mtype == 0)      { v0 = Ws1[k0*300 + col];
                                       if (k1 < 300) v1 = Ws1[k1*300 + col]; }
                else if (mtype == 1) { v0 = Ws1[(600+k0)*300 + col];
                                       if (k1 < 300) v1 = Ws1[(600+k1)*300 + col]; }
                else                 { v0 = Wu[(300+k0)*300 + col];
                                       if (k1 < 300) v1 = Wu[(300+k1)*300 + col]; }
            }
        } else {
            int e = idx - WB_POFF;
            int col = e / APITCH, p = e % APITCH;
            int k0 = 2*p, k1 = 2*p + 1;
            if (col < 900 && k0 < 300) {
                int role = col / 300, jc = col - role*300;
                if (role == 0)      { v0 = We1[k0*300 + jc];
                                      if (k1 < 300) v1 = We1[k1*300 + jc]; }
                else if (role == 1) { v0 = Ws1[(300+k0)*300 + jc];
                                      if (k1 < 300) v1 = Ws1[(300+k1)*300 + jc]; }
                else                { v0 = Wu[k0*300 + jc];
                                      if (k1 < 300) v1 = Wu[k1*300 + jc]; }
            }
        }
        float h0,l0,h1,l1;
        bsplit(v0, h0, l0);
        bsplit(v1, h1, l1);
        g_WBh[idx] = pack_bf16x2(h0, h1);
        g_WBl[idx] = pack_bf16x2(l0, l1);
    }
    // ---- one-time: hs split tables ----
    for (size_t idx = blockIdx.x*NTHREADS + tid; idx < (size_t)HSROWS*APITCH;
         idx += (size_t)nblk*NTHREADS) {
        size_t row = idx / APITCH;
        int p = (int)(idx % APITCH);
        int k0 = 2*p, k1 = 2*p + 1;
        float v0 = 0.f, v1 = 0.f;
        if (k0 < 300) {
            v0 = hs[row*HDIM + k0];
            if (k1 < 300) v1 = hs[row*HDIM + k1];
        }
        float h0,l0,h1,l1;
        bsplit(v0, h0, l0);
        bsplit(v1, h1, l1);
        g_HSh[idx] = pack_bf16x2(h0, h1);
        g_HSl[idx] = pack_bf16x2(l0, l1);
    }
    grid_bar(target, nblk);

    // ---- one-time: precompute P for ALL steps ----
    for (;;) {
        if (tid == 0) s_job = (int)atomicAdd(&g_pctr, 1u);
        __syncthreads();
        int job = s_job;
        __syncthreads();
        if (job >= PJOBS) break;
        pgemm_job(job, sm);
    }
    grid_bar(target, nblk);

    for (int t = 0; t < T_STEPS; t++) {
        // ---- phase A: mem-dependent GEMMs (tensor cores, pre-split A) ----
        for (;;) {
            if (tid == 0) s_job = (int)atomicAdd(&g_jobctr[t], 1u);
            __syncthreads();
            int job = s_job;
            __syncthreads();
            if (job >= NJOBS) break;
            gemm_job(job, sm);
        }
        grid_bar(target, nblk);

        // ---- phase B: gate (blocks 0..127) || cand precompute (rest) ----
        if (blockIdx.x < BATCH) {
            gate_job(blockIdx.x, t, mask, We2, be2, Ws2, bs2,
                     Ws1, out, s_sim, s_usage, s_red, s_ent);
        } else {
            const float4* CP4 = (const float4*)g_CP;
            const float4* Pt4 = (const float4*)(g_Pall + (size_t)t*PSZ);
            float4* cand4 = (float4*)g_cand;
            const int total = ROWS * 75;
            const int nb = nblk - BATCH;
            for (int idx = (blockIdx.x - BATCH)*NTHREADS + tid; idx < total;
                 idx += nb*NTHREADS) {
                int r  = idx / 75;
                int jq = idx - r*75;
                int b  = r / MCELLS;
                float4 ca = CP4[idx];
                float4 pa = Pt4[b*225 + 150 + jq];   // bu folded
                float4 res;
                res.x = tanh_fast(ca.x + pa.x);
                res.y = tanh_fast(ca.y + pa.y);
                res.z = tanh_fast(ca.z + pa.z);
                res.w = tanh_fast(ca.w + pa.w);
                cand4[idx] = res;
            }
        }
        grid_bar(target, nblk);

        // ---- phase C: mem update + build next-step A split tables ----
        {
            const float4* hb4 = (const float4*)(hs + (size_t)t*BATCH*HDIM);
            const float4* hn4 = (const float4*)(hs + (size_t)(t+1)*BATCH*HDIM);
            const bool more = (t + 1 < T_STEPS);
            const float4* cand4 = (const float4*)g_cand;
            float4* mem4 = (float4*)g_mem;
            const int total = ROWS * 75;
            for (int idx = blockIdx.x*NTHREADS + tid; idx < total;
                 idx += nblk*NTHREADS) {
                int r  = idx / 75;
                int jq = idx - r*75;
                int b  = r / MCELLS;
                float owv = g_ow[r], iv = g_indv[r];
                float coef = 1.f - owv - iv;
                float4 cd = cand4[idx];
                float4 h  = hb4[b*75 + jq];
                float4 mo = mem4[idx];
                float4 res;
                res.x = owv*h.x + coef*mo.x + iv*cd.x;
                res.y = owv*h.y + coef*mo.y + iv*cd.y;
                res.z = owv*h.z + coef*mo.z + iv*cd.z;
                res.w = owv*h.w + coef*mo.w + iv*cd.w;
                mem4[idx] = res;
                if (more) {
                    size_t to = (size_t)r*APITCH + jq*2;
                    float hx,lx,hy,ly,hz,lz,hw,lw;
                    bsplit(res.x,hx,lx); bsplit(res.y,hy,ly);
                    bsplit(res.z,hz,lz); bsplit(res.w,hw,lw);
                    *(uint2*)&g_AMh[to] = make_uint2(pack_bf16x2(hx,hy), pack_bf16x2(hz,hw));
                    *(uint2*)&g_AMl[to] = make_uint2(pack_bf16x2(lx,ly), pack_bf16x2(lz,lw));
                    float4 hn = hn4[b*75 + jq];
                    float mx2 = res.x*hn.x, my2 = res.y*hn.y;
                    float mz2 = res.z*hn.z, mw2 = res.w*hn.w;
                    bsplit(mx2,hx,lx); bsplit(my2,hy,ly);
                    bsplit(mz2,hz,lz); bsplit(mw2,hw,lw);
                    *(uint2*)&g_AHh[to] = make_uint2(pack_bf16x2(hx,hy), pack_bf16x2(hz,hw));
                    *(uint2*)&g_AHl[to] = make_uint2(pack_bf16x2(lx,ly), pack_bf16x2(lz,lw));
                }
            }
        }
        grid_bar(target, nblk);
    }
}

extern "C" void kernel_launch(void* const* d_in, const int* in_sizes, int n_in,
                              void* d_out, int out_size) {
    const float* hs   = (const float*)d_in[0];
    const float* mask = (const float*)d_in[1];
    const float* We1  = (const float*)d_in[2];
    const float* be1  = (const float*)d_in[3];
    const float* We2  = (const float*)d_in[4];
    const float* be2  = (const float*)d_in[5];
    const float* Ws1  = (const float*)d_in[6];
    const float* bs1  = (const float*)d_in[7];
    const float* Ws2  = (const float*)d_in[8];
    const float* bs2  = (const float*)d_in[9];
    const float* Wu   = (const float*)d_in[10];
    const float* bu   = (const float*)d_in[11];
    float* out = (float*)d_out;

    const int smemsz = (int)sizeof(SmemT);
    cudaFuncSetAttribute(k_persist, cudaFuncAttributeMaxDynamicSharedMemorySize,
                         smemsz);

    int smcount = 148;
    cudaDeviceGetAttribute(&smcount, cudaDevAttrMultiProcessorCount, 0);
    int maxb = 1;
    cudaOccupancyMaxActiveBlocksPerMultiprocessor(&maxb, k_persist, NTHREADS,
                                                  smemsz);
    if (maxb > 2) maxb = 2;
    if (maxb < 1) maxb = 1;
    int nblk = maxb * smcount;

    void *pmem, *pusg, *pcnt, *pjob, *ppc, *pamh, *paml, *pahh, *pahl;
    cudaGetSymbolAddress(&pmem, g_mem);
    cudaGetSymbolAddress(&pusg, g_usage);
    cudaGetSymbolAddress(&pcnt, g_count);
    cudaGetSymbolAddress(&pjob, g_jobctr);
    cudaGetSymbolAddress(&ppc,  g_pctr);
    cudaGetSymbolAddress(&pamh, g_AMh);
    cudaGetSymbolAddress(&paml, g_AMl);
    cudaGetSymbolAddress(&pahh, g_AHh);
    cudaGetSymbolAddress(&pahl, g_AHl);
    cudaMemsetAsync(pmem, 0, sizeof(float)*(size_t)RH);
    cudaMemsetAsync(pusg, 0, sizeof(float)*(size_t)ROWS);
    cudaMemsetAsync(pcnt, 0, sizeof(unsigned));
    cudaMemsetAsync(ppc,  0, sizeof(unsigned));
    cudaMemsetAsync(pjob, 0, sizeof(unsigned)*T_STEPS);
    cudaMemsetAsync(pamh, 0, sizeof(unsigned)*(size_t)ROWS*APITCH);
    cudaMemsetAsync(paml, 0, sizeof(unsigned)*(size_t)ROWS*APITCH);
    cudaMemsetAsync(pahh, 0, sizeof(unsigned)*(size_t)ROWS*APITCH);
    cudaMemsetAsync(pahl, 0, sizeof(unsigned)*(size_t)ROWS*APITCH);

    k_persist<<<nblk, NTHREADS, smemsz>>>(hs, mask, We1, be1, We2, be2,
                                          Ws1, bs1, Ws2, bs2, Wu, bu, out, nblk);
}